// round 11
// baseline (speedup 1.0000x reference)
#include <cuda_runtime.h>

#define Bsz 4
#define Tsz 2048
#define Csz 1024
#define Hn  16
#define Dh  64
#define BT  (Bsz * Tsz)     /* 8192 */
#define N3  (3 * Csz)       /* 3072 */

// Scratch (allocation-free rule: __device__ globals)
__device__ float g_q[Bsz * Hn * Tsz * Dh];   // [B,H,T,D]
__device__ float g_k[Bsz * Hn * Tsz * Dh];
__device__ float g_v[Bsz * Hn * Tsz * Dh];
__device__ float g_y[BT * Csz];              // [B,T,C] attention output

// ---------------------------------------------------------------------------
// GEMM 1: qkv = x @ w_attn + b_attn, scatter to g_q/g_k/g_v.
// CTA tile 128(M)x64(N), k-chunk 8, 256 thr, 8x4 per thread (acc = 32 regs
// -> multiple blocks/SM). Double-buffered smem; all fragment reads float4.
// ---------------------------------------------------------------------------
__global__ __launch_bounds__(256) void qkv_gemm(const float* __restrict__ A,
                                                const float* __restrict__ Bw,
                                                const float* __restrict__ bias)
{
    __shared__ float As[2][8][128];
    __shared__ float Bs[2][8][64];

    const int tid = threadIdx.x;
    const int bm = blockIdx.y * 128;
    const int bn = blockIdx.x * 64;
    const int tr = (tid >> 4) * 8;       // 8 rows
    const int tc = (tid & 15) * 4;       // 4 cols

    float acc[8][4];
#pragma unroll
    for (int i = 0; i < 8; i++)
#pragma unroll
        for (int j = 0; j < 4; j++) acc[i][j] = 0.f;

    const int arow = tid >> 1;            // 0..127
    const int acol = (tid & 1) * 4;       // 0 or 4
    const int brow = tid >> 5;            // 0..7
    const int bcol = (tid & 31) * 2;      // 0..62

    const float* Ap = A + (size_t)(bm + arow) * Csz + acol;
    const float* Bp = Bw + (size_t)brow * N3 + bn + bcol;

    {   // prologue: chunk 0 -> buffer 0
        float4 a4 = *(const float4*)(Ap);
        float2 b2 = *(const float2*)(Bp);
        As[0][acol + 0][arow] = a4.x;
        As[0][acol + 1][arow] = a4.y;
        As[0][acol + 2][arow] = a4.z;
        As[0][acol + 3][arow] = a4.w;
        *(float2*)&Bs[0][brow][bcol] = b2;
    }
    __syncthreads();

    const int NC = Csz / 8;
    for (int c = 0; c < NC; c++) {
        const int cur = c & 1;
        float4 a4;
        float2 b2;
        if (c + 1 < NC) {
            a4 = *(const float4*)(Ap + (c + 1) * 8);
            b2 = *(const float2*)(Bp + (size_t)(c + 1) * 8 * N3);
        }

#pragma unroll
        for (int kk = 0; kk < 8; kk++) {
            float4 af0 = *(const float4*)&As[cur][kk][tr];
            float4 af1 = *(const float4*)&As[cur][kk][tr + 4];
            float4 bg  = *(const float4*)&Bs[cur][kk][tc];
            const float af[8] = {af0.x, af0.y, af0.z, af0.w,
                                 af1.x, af1.y, af1.z, af1.w};
            const float bf[4] = {bg.x, bg.y, bg.z, bg.w};
#pragma unroll
            for (int i = 0; i < 8; i++)
#pragma unroll
                for (int j = 0; j < 4; j++) acc[i][j] += af[i] * bf[j];
        }

        if (c + 1 < NC) {
            const int nxt = cur ^ 1;
            As[nxt][acol + 0][arow] = a4.x;
            As[nxt][acol + 1][arow] = a4.y;
            As[nxt][acol + 2][arow] = a4.z;
            As[nxt][acol + 3][arow] = a4.w;
            *(float2*)&Bs[nxt][brow][bcol] = b2;
        }
        __syncthreads();
    }

#pragma unroll
    for (int i = 0; i < 8; i++) {
        const int row = bm + tr + i;
        const int bb = row >> 11;
        const int t  = row & (Tsz - 1);
#pragma unroll
        for (int j = 0; j < 4; j++) {
            const int n = bn + tc + j;
            const float val = acc[i][j] + bias[n];
            const int sec = n >> 10;
            const int c2  = n & 1023;
            const int h = c2 >> 6;
            const int d = c2 & 63;
            float* dst = (sec == 0) ? g_q : (sec == 1) ? g_k : g_v;
            dst[((bb * Hn + h) * Tsz + t) * Dh + d] = val;
        }
    }
}

// ---------------------------------------------------------------------------
// GEMM 2: out = y @ w_proj + b_proj. Same 128x64 structure.
// ---------------------------------------------------------------------------
__global__ __launch_bounds__(256) void proj_gemm(const float* __restrict__ Bw,
                                                 const float* __restrict__ bias,
                                                 float* __restrict__ out)
{
    __shared__ float As[2][8][128];
    __shared__ float Bs[2][8][64];

    const int tid = threadIdx.x;
    const int bm = blockIdx.y * 128;
    const int bn = blockIdx.x * 64;
    const int tr = (tid >> 4) * 8;
    const int tc = (tid & 15) * 4;

    float acc[8][4];
#pragma unroll
    for (int i = 0; i < 8; i++)
#pragma unroll
        for (int j = 0; j < 4; j++) acc[i][j] = 0.f;

    const int arow = tid >> 1;
    const int acol = (tid & 1) * 4;
    const int brow = tid >> 5;
    const int bcol = (tid & 31) * 2;

    const float* Ap = g_y + (size_t)(bm + arow) * Csz + acol;
    const float* Bp = Bw + (size_t)brow * Csz + bn + bcol;

    {
        float4 a4 = *(const float4*)(Ap);
        float2 b2 = *(const float2*)(Bp);
        As[0][acol + 0][arow] = a4.x;
        As[0][acol + 1][arow] = a4.y;
        As[0][acol + 2][arow] = a4.z;
        As[0][acol + 3][arow] = a4.w;
        *(float2*)&Bs[0][brow][bcol] = b2;
    }
    __syncthreads();

    const int NC = Csz / 8;
    for (int c = 0; c < NC; c++) {
        const int cur = c & 1;
        float4 a4;
        float2 b2;
        if (c + 1 < NC) {
            a4 = *(const float4*)(Ap + (c + 1) * 8);
            b2 = *(const float2*)(Bp + (size_t)(c + 1) * 8 * Csz);
        }

#pragma unroll
        for (int kk = 0; kk < 8; kk++) {
            float4 af0 = *(const float4*)&As[cur][kk][tr];
            float4 af1 = *(const float4*)&As[cur][kk][tr + 4];
            float4 bg  = *(const float4*)&Bs[cur][kk][tc];
            const float af[8] = {af0.x, af0.y, af0.z, af0.w,
                                 af1.x, af1.y, af1.z, af1.w};
            const float bf[4] = {bg.x, bg.y, bg.z, bg.w};
#pragma unroll
            for (int i = 0; i < 8; i++)
#pragma unroll
                for (int j = 0; j < 4; j++) acc[i][j] += af[i] * bf[j];
        }

        if (c + 1 < NC) {
            const int nxt = cur ^ 1;
            As[nxt][acol + 0][arow] = a4.x;
            As[nxt][acol + 1][arow] = a4.y;
            As[nxt][acol + 2][arow] = a4.z;
            As[nxt][acol + 3][arow] = a4.w;
            *(float2*)&Bs[nxt][brow][bcol] = b2;
        }
        __syncthreads();
    }

#pragma unroll
    for (int i = 0; i < 8; i++) {
        const int row = bm + tr + i;
#pragma unroll
        for (int j = 0; j < 4; j++) {
            const int n = bn + tc + j;
            out[(size_t)row * Csz + n] = acc[i][j] + bias[n];
        }
    }
}

// ---------------------------------------------------------------------------
// Flash attention (fp32, causal) — R1 structure and math order, with
// vectorized inner loops: K staged transposed (Kt[d][key], stride 68),
// P in padded buffer (stride 68), V float4 reads. Numerics identical to R1.
// Smem: Qs[64][64] + Kt[64][68] + Vs[64][64] + Ps[64][68] = 67584 B (dyn).
// ---------------------------------------------------------------------------
extern __shared__ float sm_attn[];

__global__ __launch_bounds__(256) void attn_kernel()
{
    float* Qs = sm_attn;                 // [64 q][64 d], pre-scaled by 1/8
    float* Kt = Qs + 64 * 64;            // [64 d][68]: Kt[d*68 + key]
    float* Vs = Kt + 64 * 68;            // [64 k][64 d]
    float* Ps = Vs + 64 * 64;            // [64 q][68]

    const int head = blockIdx.y;
    const int qt = blockIdx.x;
    const float* Qg = g_q + (size_t)head * (Tsz * Dh);
    const float* Kg = g_k + (size_t)head * (Tsz * Dh);
    const float* Vg = g_v + (size_t)head * (Tsz * Dh);

    const int tid = threadIdx.x;
    const int rg = tid >> 4;             // 0..15 row group
    const int cg = tid & 15;             // 0..15 col group
    const int r0 = rg * 4;
    const int c0 = cg * 4;

    float m_i[4], l_i[4], o[4][4];
#pragma unroll
    for (int i = 0; i < 4; i++) {
        m_i[i] = -1e30f;
        l_i[i] = 0.f;
#pragma unroll
        for (int j = 0; j < 4; j++) o[i][j] = 0.f;
    }

    // Load Q tile (scale folded in: 1/sqrt(64) = 0.125)
    for (int i = tid; i < 64 * 64; i += 256) {
        const int r = i >> 6, d = i & 63;
        Qs[r * 64 + d] = Qg[(size_t)(qt * 64 + r) * 64 + d] * 0.125f;
    }

    for (int kt = 0; kt <= qt; kt++) {
        __syncthreads();   // prior iter done with Kt/Vs; Q staged (first iter)
        // Stage K transposed + V row-major (float4 granularity)
        for (int f4 = tid; f4 < 64 * 16; f4 += 256) {
            const int r = f4 >> 4, c = (f4 & 15) * 4;
            float4 kv = *(const float4*)(Kg + (size_t)(kt * 64 + r) * 64 + c);
            float4 vv = *(const float4*)(Vg + (size_t)(kt * 64 + r) * 64 + c);
            Kt[(c + 0) * 68 + r] = kv.x;
            Kt[(c + 1) * 68 + r] = kv.y;
            Kt[(c + 2) * 68 + r] = kv.z;
            Kt[(c + 3) * 68 + r] = kv.w;
            *(float4*)&Vs[r * 64 + c] = vv;
        }
        __syncthreads();

        // S = Q @ K^T — vectorized over 4 d's per step; e-order = dd ascending
        float s[4][4];
#pragma unroll
        for (int i = 0; i < 4; i++)
#pragma unroll
            for (int j = 0; j < 4; j++) s[i][j] = 0.f;

        for (int dd = 0; dd < 64; dd += 4) {
            float af[4][4], bf[4][4];
#pragma unroll
            for (int i = 0; i < 4; i++) {
                float4 q4 = *(const float4*)&Qs[(r0 + i) * 64 + dd];
                af[i][0] = q4.x; af[i][1] = q4.y; af[i][2] = q4.z; af[i][3] = q4.w;
            }
#pragma unroll
            for (int e = 0; e < 4; e++) {
                float4 k4 = *(const float4*)&Kt[(dd + e) * 68 + c0];
                bf[e][0] = k4.x; bf[e][1] = k4.y; bf[e][2] = k4.z; bf[e][3] = k4.w;
            }
#pragma unroll
            for (int i = 0; i < 4; i++)
#pragma unroll
                for (int j = 0; j < 4; j++)
#pragma unroll
                    for (int e = 0; e < 4; e++)
                        s[i][j] += af[i][e] * bf[e][j];
        }

        // Causal mask (diagonal tile only)
        if (kt == qt) {
#pragma unroll
            for (int i = 0; i < 4; i++)
#pragma unroll
                for (int j = 0; j < 4; j++)
                    if (c0 + j > r0 + i) s[i][j] = -1e30f;
        }

        // Online softmax (identical to R1)
#pragma unroll
        for (int i = 0; i < 4; i++) {
            float tmax = s[i][0];
#pragma unroll
            for (int j = 1; j < 4; j++) tmax = fmaxf(tmax, s[i][j]);
#pragma unroll
            for (int off = 1; off < 16; off <<= 1)
                tmax = fmaxf(tmax, __shfl_xor_sync(0xffffffffu, tmax, off));

            const float mnew = fmaxf(m_i[i], tmax);
            const float sc = __expf(m_i[i] - mnew);
            m_i[i] = mnew;

            float tsum = 0.f;
#pragma unroll
            for (int j = 0; j < 4; j++) {
                const float p = __expf(s[i][j] - mnew);
                s[i][j] = p;
                tsum += p;
            }
#pragma unroll
            for (int off = 1; off < 16; off <<= 1)
                tsum += __shfl_xor_sync(0xffffffffu, tsum, off);

            l_i[i] = l_i[i] * sc + tsum;
#pragma unroll
            for (int j = 0; j < 4; j++) {
                o[i][j] *= sc;
                Ps[(r0 + i) * 68 + (c0 + j)] = s[i][j];
            }
        }
        // P rows r0..r0+3 are written and read within the same half-warp.
        __syncwarp();

        // O += P @ V — vectorized over 4 k's per step; e-order = kk ascending
        for (int kk = 0; kk < 64; kk += 4) {
            float af[4][4], bf[4][4];
#pragma unroll
            for (int i = 0; i < 4; i++) {
                float4 p4 = *(const float4*)&Ps[(r0 + i) * 68 + kk];
                af[i][0] = p4.x; af[i][1] = p4.y; af[i][2] = p4.z; af[i][3] = p4.w;
            }
#pragma unroll
            for (int e = 0; e < 4; e++) {
                float4 v4 = *(const float4*)&Vs[(kk + e) * 64 + c0];
                bf[e][0] = v4.x; bf[e][1] = v4.y; bf[e][2] = v4.z; bf[e][3] = v4.w;
            }
#pragma unroll
            for (int i = 0; i < 4; i++)
#pragma unroll
                for (int j = 0; j < 4; j++)
#pragma unroll
                    for (int e = 0; e < 4; e++)
                        o[i][j] += af[i][e] * bf[e][j];
        }
    }

    // Write y in [B,T,C] (head h occupies cols h*64..h*64+63)
    const int b = head >> 4;
    const int h = head & 15;
#pragma unroll
    for (int i = 0; i < 4; i++) {
        const int t = qt * 64 + r0 + i;
        const float inv = 1.f / l_i[i];
#pragma unroll
        for (int j = 0; j < 4; j++)
            g_y[((size_t)b * Tsz + t) * Csz + h * 64 + c0 + j] = o[i][j] * inv;
    }
}

// ---------------------------------------------------------------------------

extern "C" void kernel_launch(void* const* d_in, const int* in_sizes, int n_in,
                              void* d_out, int out_size)
{
    (void)in_sizes; (void)n_in; (void)out_size;
    const float* x      = (const float*)d_in[0];
    const float* w_attn = (const float*)d_in[1];
    const float* b_attn = (const float*)d_in[2];
    const float* w_proj = (const float*)d_in[3];
    const float* b_proj = (const float*)d_in[4];
    float* out = (float*)d_out;

    static const size_t ATTN_SMEM =
        (size_t)(64 * 64 + 64 * 68 + 64 * 64 + 64 * 68) * sizeof(float);
    cudaFuncSetAttribute(attn_kernel,
                         cudaFuncAttributeMaxDynamicSharedMemorySize,
                         (int)ATTN_SMEM);

    qkv_gemm<<<dim3(N3 / 64, BT / 128), 256>>>(x, w_attn, b_attn);
    attn_kernel<<<dim3(Tsz / 64, Bsz * Hn), 256, ATTN_SMEM>>>();
    proj_gemm<<<dim3(Csz / 64, BT / 128), 256>>>(w_proj, b_proj, out);
}